// round 8
// baseline (speedup 1.0000x reference)
#include <cuda_runtime.h>

// DCN cross, B=8192, D=256, L=4, collapsed algebra + software pipeline:
//   out = a_L*x0 + v_L,  a_{l+1} = a_l*(1+d_l) + c_l,  d_l = x0.W_l.
// 16 lanes/row, 2 rows/warp-task; each warp runs 2 tasks with the next
// task's x loads issued before the current task's compute (latency hiding).
// grid=296 (2 blocks/SM uniform), block=256.

constexpr int D = 256;
constexpr int L = 4;

__global__ __launch_bounds__(256)
void cross_kernel(const float* __restrict__ x,
                  const float* __restrict__ W,
                  const float* __restrict__ b_lin,
                  const float* __restrict__ bias,
                  float* __restrict__ out,
                  int ntasks)          // = B/2
{
    __shared__ float W_sm[L * D];      // 4 KB
    __shared__ float v_sm[D];
    __shared__ float c_part[8 * L];
    __shared__ float c_sm[L];

    const int tid  = threadIdx.x;
    const int warp = tid >> 5;
    const int lane = tid & 31;
    const int j    = lane & 15;        // slot within 16-lane row group
    const int sub  = lane >> 4;        // which of the 2 rows in the task

    const int nwarps = gridDim.x * 8;
    int task = blockIdx.x * 8 + warp;
    bool valid = task < ntasks;

    // ---- prologue: first x tile issues before the preamble (hidden) ----
    float4 xq[4];
    if (valid) {
        const float4* xr = reinterpret_cast<const float4*>(x + (size_t)(task * 2 + sub) * D);
        #pragma unroll
        for (int k = 0; k < 4; ++k) xq[k] = xr[k * 16 + j];
    }

    // ---- preamble (once per block): W->smem, v_L, c_l ----
    {
        float v = 0.0f;
        float cp[L];
        #pragma unroll
        for (int l = 0; l < L; ++l) {
            const float w = W[l * D + tid];
            W_sm[l * D + tid] = w;
            cp[l] = v * w;                        // c_l uses v BEFORE update
            v += b_lin[l] + bias[l * D + tid];
        }
        v_sm[tid] = v;
        #pragma unroll
        for (int o = 16; o > 0; o >>= 1) {
            #pragma unroll
            for (int l = 0; l < L; ++l)
                cp[l] += __shfl_xor_sync(0xffffffffu, cp[l], o);
        }
        if (lane == 0) {
            #pragma unroll
            for (int l = 0; l < L; ++l) c_part[warp * L + l] = cp[l];
        }
    }
    __syncthreads();
    if (tid < L) {
        float s = 0.0f;
        #pragma unroll
        for (int w8 = 0; w8 < 8; ++w8) s += c_part[w8 * L + tid];
        c_sm[tid] = s;
    }
    __syncthreads();

    // ---- loop-invariant state -> registers (epilogue has zero LDS) ----
    float c[L];
    #pragma unroll
    for (int l = 0; l < L; ++l) c[l] = c_sm[l];
    float4 vq[4];
    {
        const float4* vr = reinterpret_cast<const float4*>(v_sm);
        #pragma unroll
        for (int k = 0; k < 4; ++k) vq[k] = vr[k * 16 + j];
    }
    const float4* Wv = reinterpret_cast<const float4*>(W_sm);

    // ---- pipelined task loop ----
    while (valid) {
        const int  next  = task + nwarps;
        const bool vnext = next < ntasks;

        // issue NEXT tile's loads first — they complete behind current compute
        float4 xq2[4];
        if (vnext) {
            const float4* xr2 = reinterpret_cast<const float4*>(x + (size_t)(next * 2 + sub) * D);
            #pragma unroll
            for (int k = 0; k < 4; ++k) xq2[k] = xr2[k * 16 + j];
        }

        // dots: d_l = x0 . W_l
        float d[L];
        #pragma unroll
        for (int l = 0; l < L; ++l) {
            float a0 = 0.f, a1 = 0.f, a2 = 0.f, a3 = 0.f;
            #pragma unroll
            for (int k = 0; k < 4; ++k) {
                const float4 w = Wv[l * 64 + k * 16 + j];
                a0 = fmaf(xq[k].x, w.x, a0);
                a1 = fmaf(xq[k].y, w.y, a1);
                a2 = fmaf(xq[k].z, w.z, a2);
                a3 = fmaf(xq[k].w, w.w, a3);
            }
            d[l] = (a0 + a1) + (a2 + a3);
        }

        // 4-step width-16 ladder (reduces both rows per SHFL)
        #pragma unroll
        for (int o = 8; o > 0; o >>= 1) {
            #pragma unroll
            for (int l = 0; l < L; ++l)
                d[l] += __shfl_xor_sync(0xffffffffu, d[l], o);
        }

        // scalar recurrence
        float a = 1.0f;
        #pragma unroll
        for (int l = 0; l < L; ++l)
            a = fmaf(a, d[l], a + c[l]);          // a += a*d_l + c_l

        // epilogue: out = a*x0 + v (v in regs)
        float4* orow = reinterpret_cast<float4*>(out + (size_t)(task * 2 + sub) * D);
        #pragma unroll
        for (int k = 0; k < 4; ++k) {
            float4 o4;
            o4.x = fmaf(a, xq[k].x, vq[k].x);
            o4.y = fmaf(a, xq[k].y, vq[k].y);
            o4.z = fmaf(a, xq[k].z, vq[k].z);
            o4.w = fmaf(a, xq[k].w, vq[k].w);
            orow[k * 16 + j] = o4;
        }

        // rotate pipeline
        task  = next;
        valid = vnext;
        #pragma unroll
        for (int k = 0; k < 4; ++k) xq[k] = xq2[k];
    }
}

extern "C" void kernel_launch(void* const* d_in, const int* in_sizes, int n_in,
                              void* d_out, int out_size)
{
    const float* x     = (const float*)d_in[0];
    const float* W     = (const float*)d_in[1];
    const float* b_lin = (const float*)d_in[2];
    const float* bias  = (const float*)d_in[3];
    float* out         = (float*)d_out;

    const int B = in_sizes[0] / D;   // 8192
    const int ntasks = B / 2;        // 4096 (2 rows per warp-task)
    const int blocks = 296;          // 2 blocks/SM on 148 SMs, single wave

    cross_kernel<<<blocks, 256>>>(x, W, b_lin, bias, out, ntasks);
}

// round 9
// speedup vs baseline: 1.0370x; 1.0370x over previous
#include <cuda_runtime.h>

// DCN cross, B=8192, D=256, L=4 — collapsed algebra, barrier-free:
//   out = a_L*x0 + v_L,  a_{l+1} = a_l*(1+d_l) + c_l
//   d_l = x0.W_l  (per-row);  v_l, c_l row-independent but recomputed
//   per-warp from registers (W/bias are L1-broadcast; no smem, no syncs).
// 16 lanes/row, 2 rows/warp, 4 warps/block, grid = 1024.
// One 4-step ladder reduces d[0..3] and c[0..3] together for both rows.

constexpr int D = 256;
constexpr int L = 4;

__device__ __forceinline__ float dot4(const float4& a, const float4& b) {
    float t = a.x * b.x;
    t = fmaf(a.y, b.y, t);
    t = fmaf(a.z, b.z, t);
    t = fmaf(a.w, b.w, t);
    return t;
}

__global__ __launch_bounds__(128)
void cross_kernel(const float* __restrict__ x,
                  const float* __restrict__ W,
                  const float* __restrict__ b_lin,
                  const float* __restrict__ bias,
                  float* __restrict__ out,
                  int B)
{
    const int tid  = threadIdx.x;
    const int warp = tid >> 5;
    const int lane = tid & 31;
    const int j    = lane & 15;       // slot within 16-lane row group
    const int sub  = lane >> 4;       // row within warp
    const int row  = blockIdx.x * 8 + warp * 2 + sub;
    if (row >= B) return;

    // ---- x loads first: 4 independent LDG.128 (the only DRAM traffic) ----
    const float4* xr = reinterpret_cast<const float4*>(x + (size_t)row * D);
    float4 xq[4];
    #pragma unroll
    for (int k = 0; k < 4; ++k) xq[k] = xr[k * 16 + j];

    // ---- per-warp redundant v / c / d partials (W, bias are L1-broadcast) ----
    float4 vv[4] = { {0,0,0,0}, {0,0,0,0}, {0,0,0,0}, {0,0,0,0} };
    float red[2 * L];   // [0..3] = d partials, [4..7] = c partials

    #pragma unroll
    for (int l = 0; l < L; ++l) {
        const float4* Wr = reinterpret_cast<const float4*>(W + l * D);
        const float4* Br = reinterpret_cast<const float4*>(bias + l * D);
        float4 w4[4], b4[4];
        #pragma unroll
        for (int k = 0; k < 4; ++k) { w4[k] = Wr[k * 16 + j]; b4[k] = Br[k * 16 + j]; }

        float dp = 0.f, cp = 0.f;
        #pragma unroll
        for (int k = 0; k < 4; ++k) {
            dp += dot4(xq[k], w4[k]);
            cp += dot4(vv[k], w4[k]);          // c_l uses v BEFORE the update
        }
        red[l]     = dp;
        red[L + l] = cp;

        const float bl = b_lin[l];
        #pragma unroll
        for (int k = 0; k < 4; ++k) {
            vv[k].x += bl + b4[k].x;
            vv[k].y += bl + b4[k].y;
            vv[k].z += bl + b4[k].z;
            vv[k].w += bl + b4[k].w;
        }
    }

    // ---- single 4-step width-16 ladder reduces all 8 values, both rows ----
    #pragma unroll
    for (int o = 8; o > 0; o >>= 1) {
        #pragma unroll
        for (int t = 0; t < 2 * L; ++t)
            red[t] += __shfl_xor_sync(0xffffffffu, red[t], o);
    }

    // ---- scalar recurrence: a += a*d_l + c_l ----
    float a = 1.0f;
    #pragma unroll
    for (int l = 0; l < L; ++l)
        a = fmaf(a, red[l], a + red[L + l]);

    // ---- epilogue: out = a*x0 + v_L (all registers) ----
    float4* orow = reinterpret_cast<float4*>(out + (size_t)row * D);
    #pragma unroll
    for (int k = 0; k < 4; ++k) {
        float4 o4;
        o4.x = fmaf(a, xq[k].x, vv[k].x);
        o4.y = fmaf(a, xq[k].y, vv[k].y);
        o4.z = fmaf(a, xq[k].z, vv[k].z);
        o4.w = fmaf(a, xq[k].w, vv[k].w);
        orow[k * 16 + j] = o4;
    }
}

extern "C" void kernel_launch(void* const* d_in, const int* in_sizes, int n_in,
                              void* d_out, int out_size)
{
    const float* x     = (const float*)d_in[0];
    const float* W     = (const float*)d_in[1];
    const float* b_lin = (const float*)d_in[2];
    const float* bias  = (const float*)d_in[3];
    float* out         = (float*)d_out;

    const int B = in_sizes[0] / D;        // 8192
    const int blocks = (B + 7) / 8;       // 1024 blocks of 128 threads (8 rows each)

    cross_kernel<<<blocks, 128>>>(x, W, b_lin, bias, out, B);
}